// round 14
// baseline (speedup 1.0000x reference)
#include <cuda_runtime.h>
#include <cstdint>

#define NN   20000
#define EE   320000
#define FIN  512
#define HID  64
#define LL   9
#define NTPL 10
#define NTN  8
#define NCLS 6
#define NBD  8       // nodes per k_dist block
#define SLOT 64      // max in-degree bucket

typedef unsigned long long u64;

// -------- scratch (no cudaMalloc allowed) --------
__device__ float g_bufA[NN * HID];
__device__ float g_bufB[NN * HID];
__device__ float g_bufC[NN * HID];
__device__ int   g_cnt[NN];
__device__ int   g_csrc[NN * SLOT];
__device__ float g_R[NN * 80];     // ||h||^2 + ||f||^2 - 2 h@f^T

// ---------------- f32x2 packed helpers ----------------
__device__ __forceinline__ u64 pk2(float lo, float hi) {
    u64 r; asm("mov.b64 %0,{%1,%2};" : "=l"(r) : "f"(lo), "f"(hi)); return r;
}
__device__ __forceinline__ u64 pk1(float x) {
    u64 r; asm("mov.b64 %0,{%1,%1};" : "=l"(r) : "f"(x)); return r;
}
__device__ __forceinline__ void upk(u64 v, float& lo, float& hi) {
    asm("mov.b64 {%0,%1},%2;" : "=f"(lo), "=f"(hi) : "l"(v));
}
__device__ __forceinline__ u64 fma2(u64 a, u64 b, u64 c) {
    u64 d; asm("fma.rn.f32x2 %0,%1,%2,%3;" : "=l"(d) : "l"(a), "l"(b), "l"(c)); return d;
}
__device__ __forceinline__ u64 mul2(u64 a, u64 b) {
    u64 d; asm("mul.rn.f32x2 %0,%1,%2;" : "=l"(d) : "l"(a), "l"(b)); return d;
}
__device__ __forceinline__ u64 add2(u64 a, u64 b) {
    u64 d; asm("add.rn.f32x2 %0,%1,%2;" : "=l"(d) : "l"(a), "l"(b)); return d;
}
__device__ __forceinline__ float ex2f(float x) {
    float r; asm("ex2.approx.f32 %0,%1;" : "=f"(r) : "f"(x)); return r;
}

// ---------------- bucket fill ----------------
__global__ void k_fill(const int* __restrict__ src, const int* __restrict__ dst) {
    int e = blockIdx.x * blockDim.x + threadIdx.x;
    if (e < EE) {
        int d = dst[e];
        int slot = atomicAdd(&g_cnt[d], 1);
        g_csrc[d * SLOT + slot] = src[e];
    }
}

// ---------------- cp.async helpers ----------------
__device__ __forceinline__ void cp16(uint32_t sdst, const void* gsrc, bool pred) {
    int sz = pred ? 16 : 0;
    asm volatile("cp.async.cg.shared.global [%0], [%1], 16, %2;\n"
                 :: "r"(sdst), "l"(gsrc), "r"(sz));
}
__device__ __forceinline__ void cp_commit() {
    asm volatile("cp.async.commit_group;\n");
}
template <int N>
__device__ __forceinline__ void cp_wait() {
    asm volatile("cp.async.wait_group %0;\n" :: "n"(N));
}

// ---------------- GEMM: oXW = (A[M,K] @ W[K,64]) * rsqrt(cnt+1)  (f32x2-packed, double-buffered) ----------------
#define AS_STRIDE 68
#define AS_TILE  (64 * AS_STRIDE)
#define BS_TILE  (64 * 64)
#define GEMM_SMEM ((2 * AS_TILE + 2 * BS_TILE) * 4)

__global__ __launch_bounds__(128) void k_gemm(
    const float* __restrict__ A, const float* __restrict__ W,
    float* __restrict__ oXW, int M, int K, int lda)
{
    extern __shared__ float smem[];
    float* As = smem;
    float* Bs = smem + 2 * AS_TILE;
    const uint32_t sAs = (uint32_t)__cvta_generic_to_shared(As);
    const uint32_t sBs = (uint32_t)__cvta_generic_to_shared(Bs);

    const int t  = threadIdx.x;
    const int tx = t & 15, ty = t >> 4;
    const int row0 = blockIdx.x * 64;

    u64 accp[8][2];
#pragma unroll
    for (int i = 0; i < 8; i++) { accp[i][0] = 0ull; accp[i][1] = 0ull; }

#pragma unroll
    for (int p = 0; p < 8; p++) {
        int v = t + 128 * p;
        int r = v >> 4, c4 = v & 15;
        int gr = row0 + r;
        cp16(sAs + (r * AS_STRIDE + c4 * 4) * 4,
             A + (size_t)gr * lda + c4 * 4, gr < M);
    }
#pragma unroll
    for (int p = 0; p < 8; p++) {
        int v = t + 128 * p;
        int r = v >> 4, c4 = v & 15;
        cp16(sBs + (r * 64 + c4 * 4) * 4,
             W + (size_t)r * HID + c4 * 4, true);
    }
    cp_commit();

    int buf = 0;
    for (int kt = 0; kt < K; kt += 64, buf ^= 1) {
        if (kt + 64 < K) {
            int nb = buf ^ 1;
#pragma unroll
            for (int p = 0; p < 8; p++) {
                int v = t + 128 * p;
                int r = v >> 4, c4 = v & 15;
                int gr = row0 + r;
                cp16(sAs + (nb * AS_TILE + r * AS_STRIDE + c4 * 4) * 4,
                     A + (size_t)gr * lda + kt + 64 + c4 * 4, gr < M);
            }
#pragma unroll
            for (int p = 0; p < 8; p++) {
                int v = t + 128 * p;
                int r = v >> 4, c4 = v & 15;
                cp16(sBs + (nb * BS_TILE + r * 64 + c4 * 4) * 4,
                     W + (size_t)(kt + 64 + r) * HID + c4 * 4, true);
            }
            cp_commit();
            cp_wait<1>();
        } else {
            cp_wait<0>();
        }
        __syncthreads();

        const float* Ab = As + buf * AS_TILE;
        const float* Bb = Bs + buf * BS_TILE;
#pragma unroll
        for (int k = 0; k < 64; k += 4) {
            float4 a4[8];
            u64 b2[4][2];
#pragma unroll
            for (int i = 0; i < 8; i++) a4[i] = *(const float4*)&Ab[(ty * 8 + i) * AS_STRIDE + k];
#pragma unroll
            for (int kk = 0; kk < 4; kk++) {
                b2[kk][0] = *(const u64*)&Bb[(k + kk) * 64 + tx * 4];
                b2[kk][1] = *(const u64*)&Bb[(k + kk) * 64 + tx * 4 + 2];
            }
#pragma unroll
            for (int i = 0; i < 8; i++) {
                u64 ax = pk1(a4[i].x);
                accp[i][0] = fma2(ax, b2[0][0], accp[i][0]);
                accp[i][1] = fma2(ax, b2[0][1], accp[i][1]);
                u64 ay = pk1(a4[i].y);
                accp[i][0] = fma2(ay, b2[1][0], accp[i][0]);
                accp[i][1] = fma2(ay, b2[1][1], accp[i][1]);
                u64 az = pk1(a4[i].z);
                accp[i][0] = fma2(az, b2[2][0], accp[i][0]);
                accp[i][1] = fma2(az, b2[2][1], accp[i][1]);
                u64 aw = pk1(a4[i].w);
                accp[i][0] = fma2(aw, b2[3][0], accp[i][0]);
                accp[i][1] = fma2(aw, b2[3][1], accp[i][1]);
            }
        }
        __syncthreads();
    }
#pragma unroll
    for (int i = 0; i < 8; i++) {
        int gr = row0 + ty * 8 + i;
        if (gr < M) {
            float dv = rsqrtf((float)g_cnt[gr] + 1.0f);
            float4 o;
            float lo, hi;
            upk(accp[i][0], lo, hi); o.x = lo * dv; o.y = hi * dv;
            upk(accp[i][1], lo, hi); o.z = lo * dv; o.w = hi * dv;
            *(float4*)(oXW + (size_t)gr * HID + tx * 4) = o;
        }
    }
}

// ---------------- gather 1 (float4, MLP 8): h[d] = relu( bias + dinv[d]*(xws[d] + sum_in xws[s]) ) ----------------
__global__ __launch_bounds__(256) void k_gather(
    const float4* __restrict__ xws4, const float4* __restrict__ bias4,
    float4* __restrict__ h4)
{
    int d = blockIdx.x * 16 + (threadIdx.x >> 4);
    int f = threadIdx.x & 15;
    int cnt = g_cnt[d];
    const int* lst = g_csrc + (size_t)d * SLOT;
    float4 acc[8];
    acc[0] = xws4[(size_t)d * 16 + f];
#pragma unroll
    for (int j = 1; j < 8; j++) acc[j] = make_float4(0.f, 0.f, 0.f, 0.f);
    int e = 0;
    for (; e + 7 < cnt; e += 8) {
        int s[8];
#pragma unroll
        for (int j = 0; j < 8; j++) s[j] = lst[e + j];
#pragma unroll
        for (int j = 0; j < 8; j++) {
            float4 v = xws4[(size_t)s[j] * 16 + f];
            acc[j].x += v.x; acc[j].y += v.y; acc[j].z += v.z; acc[j].w += v.w;
        }
    }
    for (; e + 1 < cnt; e += 2) {
        int s0 = lst[e], s1 = lst[e + 1];
        float4 v0 = xws4[(size_t)s0 * 16 + f];
        float4 v1 = xws4[(size_t)s1 * 16 + f];
        acc[0].x += v0.x; acc[0].y += v0.y; acc[0].z += v0.z; acc[0].w += v0.w;
        acc[1].x += v1.x; acc[1].y += v1.y; acc[1].z += v1.z; acc[1].w += v1.w;
    }
    if (e < cnt) {
        float4 v = xws4[(size_t)lst[e] * 16 + f];
        acc[0].x += v.x; acc[0].y += v.y; acc[0].z += v.z; acc[0].w += v.w;
    }
#pragma unroll
    for (int j = 1; j < 8; j++) {
        acc[0].x += acc[j].x; acc[0].y += acc[j].y;
        acc[0].z += acc[j].z; acc[0].w += acc[j].w;
    }
    float dv = rsqrtf((float)cnt + 1.0f);
    float4 b = bias4[f];
    float4 o;
    o.x = fmaxf(acc[0].x * dv + b.x, 0.f);
    o.y = fmaxf(acc[0].y * dv + b.y, 0.f);
    o.z = fmaxf(acc[0].z * dv + b.z, 0.f);
    o.w = fmaxf(acc[0].w * dv + b.w, 0.f);
    h4[(size_t)d * 16 + f] = o;
}

// ---------------- gather 2 fused with R-precompute ----------------
// h[d] = bias + dinv[d]*(xws[d] + sum_in xws[s])   (no relu)
// R[d, tm] = ||h[d]||^2 + ||tfeat[tm]||^2 - 2 h[d].tfeat[tm]
__global__ __launch_bounds__(256) void k_gather_pr(
    const float4* __restrict__ xws4, const float4* __restrict__ bias4,
    float4* __restrict__ h4, const float* __restrict__ tfeat)
{
    __shared__ float hs[16][68];      // 16 nodes x 64 (+pad), row 272B aligned
    __shared__ float tfs[64][81];     // transposed [k][tm]
    __shared__ float tnl[80];

    const int tid = threadIdx.x;
    int d = blockIdx.x * 16 + (tid >> 4);
    int f = tid & 15;

    // stage tfeat while gather loads are in flight
    for (int q = tid; q < 80 * 64; q += 256) {
        int tm = q >> 6, k = q & 63;
        tfs[k][tm] = tfeat[q];
    }

    int cnt = g_cnt[d];
    const int* lst = g_csrc + (size_t)d * SLOT;
    float4 acc[8];
    acc[0] = xws4[(size_t)d * 16 + f];
#pragma unroll
    for (int j = 1; j < 8; j++) acc[j] = make_float4(0.f, 0.f, 0.f, 0.f);
    int e = 0;
    for (; e + 7 < cnt; e += 8) {
        int s[8];
#pragma unroll
        for (int j = 0; j < 8; j++) s[j] = lst[e + j];
#pragma unroll
        for (int j = 0; j < 8; j++) {
            float4 v = xws4[(size_t)s[j] * 16 + f];
            acc[j].x += v.x; acc[j].y += v.y; acc[j].z += v.z; acc[j].w += v.w;
        }
    }
    for (; e + 1 < cnt; e += 2) {
        int s0 = lst[e], s1 = lst[e + 1];
        float4 v0 = xws4[(size_t)s0 * 16 + f];
        float4 v1 = xws4[(size_t)s1 * 16 + f];
        acc[0].x += v0.x; acc[0].y += v0.y; acc[0].z += v0.z; acc[0].w += v0.w;
        acc[1].x += v1.x; acc[1].y += v1.y; acc[1].z += v1.z; acc[1].w += v1.w;
    }
    if (e < cnt) {
        float4 v = xws4[(size_t)lst[e] * 16 + f];
        acc[0].x += v.x; acc[0].y += v.y; acc[0].z += v.z; acc[0].w += v.w;
    }
#pragma unroll
    for (int j = 1; j < 8; j++) {
        acc[0].x += acc[j].x; acc[0].y += acc[j].y;
        acc[0].z += acc[j].z; acc[0].w += acc[j].w;
    }
    float dv = rsqrtf((float)cnt + 1.0f);
    float4 b = bias4[f];
    float4 o;
    o.x = acc[0].x * dv + b.x;
    o.y = acc[0].y * dv + b.y;
    o.z = acc[0].z * dv + b.z;
    o.w = acc[0].w * dv + b.w;
    h4[(size_t)d * 16 + f] = o;
    *(float4*)&hs[tid >> 4][f * 4] = o;
    __syncthreads();

    if (tid < 80) {
        float s = 0.f;
#pragma unroll
        for (int k = 0; k < 64; k++) { float v = tfs[k][tid]; s += v * v; }
        tnl[tid] = s;
    }
    __syncthreads();

    // R phase: node = tid>>4, template group tg = tid&15 -> templates tg*5..tg*5+4
    const int node = tid >> 4;
    const int tg   = tid & 15;
    float racc[5];
    float hn2 = 0.f;
#pragma unroll
    for (int c = 0; c < 5; c++) racc[c] = 0.f;
#pragma unroll
    for (int k = 0; k < 64; k++) {
        float a = hs[node][k];
        hn2 += a * a;
#pragma unroll
        for (int c = 0; c < 5; c++)
            racc[c] += a * tfs[k][tg * 5 + c];
    }
    const int gnode = blockIdx.x * 16 + node;
#pragma unroll
    for (int c = 0; c < 5; c++)
        g_R[(size_t)gnode * 80 + tg * 5 + c] = hn2 + tnl[tg * 5 + c] - 2.f * racc[c];
}

// ---------------- FGW distances: split-m (2 threads per node x template), occ 4 ----------------
__global__ __launch_bounds__(160, 4) void k_dist(
    const float* __restrict__ h,
    const int*   __restrict__ nbr_idx,
    const float* __restrict__ nbr_mask,
    const float* __restrict__ C_local,
    const float* __restrict__ tadj,     // [10,8,8]
    const float* __restrict__ Wlin,     // [74,6]
    const float* __restrict__ blin,
    float* __restrict__ out)
{
    __shared__ float C1s[NBD * 81];
    __shared__ u64   C2p[NTPL * 33];    // stride 33 -> distinct banks per template
    __shared__ float h1sh[NBD * 9];
    __shared__ float f1h1[NBD * 9];
    __shared__ float ysh[NBD * NTPL];
    __shared__ int   idxs[NBD * 9];

    const int tid = threadIdx.x;
    const int sub = tid & 1;            // m half: sub*4 .. sub*4+3
    const int pid = tid >> 1;           // 0..79
    const int nl  = pid / 10;
    const int tpl = pid % 10;
    const int node0 = blockIdx.x * NBD;
    const unsigned FULL = 0xffffffffu;

    const float LOG2E = 1.4426950408889634f;

    // ---- cooperative setup ----
    for (int q = tid; q < 320; q += 160) {
        int tt = q >> 5, rem = q & 31;
        C2p[tt * 33 + rem] = pk2(tadj[2 * q], tadj[2 * q + 1]);
    }
    for (int q = tid; q < NBD * 9; q += 160) {
        int nn = q / 9, i = q % 9;
        idxs[nn * 9 + i] = (i == 0) ? (node0 + nn) : nbr_idx[(node0 + nn) * 8 + i - 1];
    }
    for (int q = tid; q < NBD * 81; q += 160)
        C1s[q] = C_local[(size_t)node0 * 81 + q];
    for (int q = tid; q < NBD * 9; q += 160) {
        int nn = q / 9, i = q % 9;
        float s = 0.f;
#pragma unroll
        for (int k = 0; k < 9; k++) s += nbr_mask[(node0 + nn) * 9 + k];
        h1sh[nn * 9 + i] = nbr_mask[(node0 + nn) * 9 + i] / s;
    }
    __syncthreads();
    for (int q = tid; q < NBD * 9; q += 160) {
        int nn = q / 9, i = q % 9;
        float s = 0.f;
#pragma unroll
        for (int k = 0; k < 9; k++) s += C1s[nn * 81 + i * 9 + k] * h1sh[nn * 9 + k];
        f1h1[nn * 9 + i] = s;
    }
    __syncthreads();

    const int c2b = tpl * 33 + 2 * sub;     // this thread's two mp columns at +0, +1
    const u64 NEG5L = pk1(-5.f * LOG2E);
    const u64 CL2   = pk1(10.f * LOG2E);

    // f2p[l] = (sum_k C2[k,m]^2)/8 ; qp[l] = 0.125*sum_k C2[k,m]  for local m pairs
    u64 f2p[2], qp[2];
    {
        const u64 EIGHTH = pk1(0.125f);
#pragma unroll
        for (int l = 0; l < 2; l++) {
            u64 c0 = C2p[c2b + l];
            u64 sq = mul2(c0, c0);
            u64 sl = c0;
#pragma unroll
            for (int k = 1; k < 8; k++) {
                u64 c = C2p[c2b + k * 4 + l];
                sq = fma2(c, c, sq);
                sl = add2(sl, c);
            }
            f2p[l] = mul2(sq, EIGHTH);
            qp[l]  = mul2(sl, EIGHTH);
        }
    }

    float h1r[9];
#pragma unroll
    for (int i = 0; i < 9; i++) h1r[i] = h1sh[nl * 9 + i];

    u64 Tp[18];    // coupling T / A2 (local m half)
    u64 TC[18];    // T @ C2 (local m half)

#pragma unroll 1
    for (int outer = 0; outer < 3; outer++) {
        if (outer == 0) {
            // rank-1: E = f1h1 (x) q -> A2 = ex2(S + CL2*fi*q)
            u64 qC[2] = { mul2(qp[0], CL2), mul2(qp[1], CL2) };
#pragma unroll
            for (int i = 0; i < 9; i++) {
                int id = idxs[nl * 9 + i];
                float4 rq = *(const float4*)(g_R + (size_t)id * 80 + tpl * 8 + 4 * sub);
                u64 rr[2] = { pk2(rq.x, rq.y), pk2(rq.z, rq.w) };
                u64 fi2 = pk1(f1h1[nl * 9 + i]);
#pragma unroll
                for (int l = 0; l < 2; l++) {
                    u64 sp = mul2(NEG5L, add2(rr[l], add2(fi2, f2p[l])));
                    u64 arg = fma2(fi2, qC[l], sp);
                    float lo, hi; upk(arg, lo, hi);
                    Tp[i * 2 + l] = pk2(ex2f(lo), ex2f(hi));
                }
            }
        } else {
            // TC = T@C2: mirror the other half of T via pair shuffles, k-outer GEMM
#pragma unroll
            for (int i = 0; i < 9; i++) {
                float tl[4], to_[4];
                upk(Tp[i * 2 + 0], tl[0], tl[1]);
                upk(Tp[i * 2 + 1], tl[2], tl[3]);
#pragma unroll
                for (int j = 0; j < 4; j++)
                    to_[j] = __shfl_xor_sync(FULL, tl[j], 1);
                float tv[8];
#pragma unroll
                for (int j = 0; j < 4; j++) {
                    tv[j]     = sub ? to_[j] : tl[j];
                    tv[j + 4] = sub ? tl[j] : to_[j];
                }
                // two-accumulator split over k to halve the dependent chain
                u64 a0a = mul2(pk1(tv[0]), C2p[c2b]);
                u64 a1a = mul2(pk1(tv[0]), C2p[c2b + 1]);
                u64 a0b = mul2(pk1(tv[1]), C2p[c2b + 4]);
                u64 a1b = mul2(pk1(tv[1]), C2p[c2b + 5]);
#pragma unroll
                for (int k = 2; k < 8; k += 2) {
                    u64 ta = pk1(tv[k]);
                    a0a = fma2(ta, C2p[c2b + k * 4], a0a);
                    a1a = fma2(ta, C2p[c2b + k * 4 + 1], a1a);
                    u64 tb = pk1(tv[k + 1]);
                    a0b = fma2(tb, C2p[c2b + (k + 1) * 4], a0b);
                    a1b = fma2(tb, C2p[c2b + (k + 1) * 4 + 1], a1b);
                }
                TC[i * 2 + 0] = add2(a0a, a0b);
                TC[i * 2 + 1] = add2(a1a, a1b);
            }
            // per row: E = C1 @ TC (split chains) ; A2 = ex2(S + CL2*E)
#pragma unroll
            for (int i = 0; i < 9; i++) {
                const float* c1 = C1s + nl * 81 + i * 9;
                u64 ck = pk1(c1[0]);
                u64 e0a = mul2(ck, TC[0]), e1a = mul2(ck, TC[1]);
                ck = pk1(c1[1]);
                u64 e0b = mul2(ck, TC[2]), e1b = mul2(ck, TC[3]);
#pragma unroll
                for (int k = 2; k < 8; k += 2) {
                    u64 ca = pk1(c1[k]);
                    e0a = fma2(ca, TC[k * 2 + 0], e0a);
                    e1a = fma2(ca, TC[k * 2 + 1], e1a);
                    u64 cb = pk1(c1[k + 1]);
                    e0b = fma2(cb, TC[(k + 1) * 2 + 0], e0b);
                    e1b = fma2(cb, TC[(k + 1) * 2 + 1], e1b);
                }
                {
                    u64 c8 = pk1(c1[8]);
                    e0a = fma2(c8, TC[16], e0a);
                    e1a = fma2(c8, TC[17], e1a);
                }
                u64 e0 = add2(e0a, e0b);
                u64 e1 = add2(e1a, e1b);
                int id = idxs[nl * 9 + i];
                float4 rq = *(const float4*)(g_R + (size_t)id * 80 + tpl * 8 + 4 * sub);
                u64 rr[2] = { pk2(rq.x, rq.y), pk2(rq.z, rq.w) };
                u64 fi2 = pk1(f1h1[nl * 9 + i]);
                u64 ee[2] = { e0, e1 };
#pragma unroll
                for (int l = 0; l < 2; l++) {
                    u64 sp = mul2(NEG5L, add2(rr[l], add2(fi2, f2p[l])));
                    u64 arg = fma2(CL2, ee[l], sp);
                    float lo, hi; upk(arg, lo, hi);
                    Tp[i * 2 + l] = pk2(ex2f(lo), ex2f(hi));
                }
            }
        }
        // sinkhorn on A2 (=Tp); row sums need the pair's half via 1 shfl
        u64 vp[2] = { pk1(1.f), pk1(1.f) };
        float ui[9];
#pragma unroll 1
        for (int it = 0; it < 5; it++) {
#pragma unroll
            for (int i = 0; i < 9; i++) {
                u64 sp = mul2(Tp[i * 2 + 0], vp[0]);
                sp = fma2(Tp[i * 2 + 1], vp[1], sp);
                float lo, hi; upk(sp, lo, hi);
                float part = lo + hi;
                part += __shfl_xor_sync(FULL, part, 1);
                ui[i] = __fdividef(h1r[i], part + 1e-16f);
            }
            // column sums with two-accumulator split over i
            u64 u0 = pk1(ui[0]);
            u64 sc0a = mul2(u0, Tp[0]), sc1a = mul2(u0, Tp[1]);
            u64 u1 = pk1(ui[1]);
            u64 sc0b = mul2(u1, Tp[2]), sc1b = mul2(u1, Tp[3]);
#pragma unroll
            for (int i = 2; i < 8; i += 2) {
                u64 ua = pk1(ui[i]);
                sc0a = fma2(ua, Tp[i * 2 + 0], sc0a);
                sc1a = fma2(ua, Tp[i * 2 + 1], sc1a);
                u64 ub = pk1(ui[i + 1]);
                sc0b = fma2(ub, Tp[(i + 1) * 2 + 0], sc0b);
                sc1b = fma2(ub, Tp[(i + 1) * 2 + 1], sc1b);
            }
            {
                u64 u8 = pk1(ui[8]);
                sc0a = fma2(u8, Tp[16], sc0a);
                sc1a = fma2(u8, Tp[17], sc1a);
            }
            u64 sc0 = add2(sc0a, sc0b);
            u64 sc1 = add2(sc1a, sc1b);
            {
                float lo, hi; upk(sc0, lo, hi);
                vp[0] = pk2(__fdividef(0.125f, lo + 1e-16f),
                            __fdividef(0.125f, hi + 1e-16f));
                upk(sc1, lo, hi);
                vp[1] = pk2(__fdividef(0.125f, lo + 1e-16f),
                            __fdividef(0.125f, hi + 1e-16f));
            }
        }
        // T = u * A2 * v
#pragma unroll
        for (int i = 0; i < 9; i++) {
            u64 u2 = pk1(ui[i]);
            Tp[i * 2 + 0] = mul2(mul2(u2, Tp[i * 2 + 0]), vp[0]);
            Tp[i * 2 + 1] = mul2(mul2(u2, Tp[i * 2 + 1]), vp[1]);
        }
    }

    // ---- final objective: obj = (-0.1*ln2)*sum(T∘S) - sum((C1^T@T)∘(T@C2)) ----
    u64 accS = pk1(0.f);
#pragma unroll
    for (int i = 0; i < 9; i++) {
        int id = idxs[nl * 9 + i];
        float4 rq = *(const float4*)(g_R + (size_t)id * 80 + tpl * 8 + 4 * sub);
        u64 rr[2] = { pk2(rq.x, rq.y), pk2(rq.z, rq.w) };
        u64 fi2 = pk1(f1h1[nl * 9 + i]);
#pragma unroll
        for (int l = 0; l < 2; l++) {
            u64 sp = mul2(NEG5L, add2(rr[l], add2(fi2, f2p[l])));
            accS = fma2(Tp[i * 2 + l], sp, accS);
        }
    }
    // TC = T@C2 (mirror + k-outer)
#pragma unroll
    for (int i = 0; i < 9; i++) {
        float tl[4], to_[4];
        upk(Tp[i * 2 + 0], tl[0], tl[1]);
        upk(Tp[i * 2 + 1], tl[2], tl[3]);
#pragma unroll
        for (int j = 0; j < 4; j++)
            to_[j] = __shfl_xor_sync(FULL, tl[j], 1);
        float tv[8];
#pragma unroll
        for (int j = 0; j < 4; j++) {
            tv[j]     = sub ? to_[j] : tl[j];
            tv[j + 4] = sub ? tl[j] : to_[j];
        }
        u64 a0 = mul2(pk1(tv[0]), C2p[c2b]);
        u64 a1 = mul2(pk1(tv[0]), C2p[c2b + 1]);
#pragma unroll
        for (int k = 1; k < 8; k++) {
            u64 t2 = pk1(tv[k]);
            a0 = fma2(t2, C2p[c2b + k * 4], a0);
            a1 = fma2(t2, C2p[c2b + k * 4 + 1], a1);
        }
        TC[i * 2 + 0] = a0;
        TC[i * 2 + 1] = a1;
    }
    // accE = sum_k (C1^T@T)[k] . TC[k]  (V rows on the fly, local m)
    u64 accE = pk1(0.f);
#pragma unroll
    for (int k = 0; k < 9; k++) {
        const float* c1 = C1s + nl * 81 + k;    // column k, stride 9
        u64 ck = pk1(c1[0]);
        u64 v0 = mul2(ck, Tp[0]), v1 = mul2(ck, Tp[1]);
#pragma unroll
        for (int i = 1; i < 9; i++) {
            ck = pk1(c1[i * 9]);
            v0 = fma2(ck, Tp[i * 2 + 0], v0);
            v1 = fma2(ck, Tp[i * 2 + 1], v1);
        }
        accE = fma2(v0, TC[k * 2 + 0], accE);
        accE = fma2(v1, TC[k * 2 + 1], accE);
    }
    {
        float slo, shi, elo, ehi;
        upk(accS, slo, shi); upk(accE, elo, ehi);
        float val = -0.06931471805599453f * (slo + shi) - (elo + ehi);
        val += __shfl_xor_sync(FULL, val, 1);
        if (sub == 0) ysh[nl * 10 + tpl] = val;
    }
    __syncthreads();

    // head: out = relu(concat(h, y) @ Wlin + blin)
    if (tid < NBD * NCLS) {
        int nn = tid / NCLS, c = tid % NCLS;
        float acc = blin[c];
#pragma unroll 8
        for (int k = 0; k < HID; k++)
            acc += h[(size_t)(node0 + nn) * HID + k] * Wlin[k * NCLS + c];
#pragma unroll
        for (int t = 0; t < NTPL; t++)
            acc += ysh[nn * 10 + t] * Wlin[(HID + t) * NCLS + c];
        out[(node0 + nn) * NCLS + c] = fmaxf(acc, 0.f);
    }
}

// ---------------- launch ----------------
extern "C" void kernel_launch(void* const* d_in, const int* in_sizes, int n_in,
                              void* d_out, int out_size)
{
    const float* x     = (const float*)d_in[0];
    const int*   ei    = (const int*)  d_in[1];
    const int*   nbr   = (const int*)  d_in[2];
    const float* mask  = (const float*)d_in[3];
    const float* Cl    = (const float*)d_in[4];
    const float* W1    = (const float*)d_in[5];
    const float* b1    = (const float*)d_in[6];
    const float* W2    = (const float*)d_in[7];
    const float* b2    = (const float*)d_in[8];
    const float* tadj  = (const float*)d_in[9];
    const float* tfeat = (const float*)d_in[10];
    const float* Wlin  = (const float*)d_in[11];
    const float* blin  = (const float*)d_in[12];
    float* out = (float*)d_out;

    const int* src = ei;
    const int* dst = ei + EE;

    void *pA, *pB, *pC, *pCnt;
    cudaGetSymbolAddress(&pA, g_bufA);
    cudaGetSymbolAddress(&pB, g_bufB);
    cudaGetSymbolAddress(&pC, g_bufC);
    cudaGetSymbolAddress(&pCnt, g_cnt);
    float* bufA = (float*)pA;
    float* bufB = (float*)pB;
    float* bufC = (float*)pC;

    cudaFuncSetAttribute(k_gemm, cudaFuncAttributeMaxDynamicSharedMemorySize, GEMM_SMEM);

    cudaMemsetAsync(pCnt, 0, NN * sizeof(int));
    k_fill<<<(EE + 255) / 256, 256>>>(src, dst);

    k_gemm<<<(NN + 63) / 64, 128, GEMM_SMEM>>>(x, W1, bufA, NN, FIN, FIN);
    k_gather<<<NN / 16, 256>>>((const float4*)bufA, (const float4*)b1, (float4*)bufB);

    k_gemm<<<(NN + 63) / 64, 128, GEMM_SMEM>>>(bufB, W2, bufA, NN, HID, HID);
    k_gather_pr<<<NN / 16, 256>>>((const float4*)bufA, (const float4*)b2, (float4*)bufC, tfeat);

    k_dist<<<NN / NBD, 160>>>(bufC, nbr, mask, Cl, tadj, Wlin, blin, out);
}

// round 15
// speedup vs baseline: 1.0495x; 1.0495x over previous
#include <cuda_runtime.h>
#include <cstdint>

#define NN   20000
#define EE   320000
#define FIN  512
#define HID  64
#define LL   9
#define NTPL 10
#define NTN  8
#define NCLS 6
#define NBD  8       // nodes per k_dist block
#define SLOT 64      // max in-degree bucket

typedef unsigned long long u64;

// -------- scratch (no cudaMalloc allowed) --------
__device__ float g_bufA[NN * HID];
__device__ float g_bufB[NN * HID];
__device__ float g_bufC[NN * HID];
__device__ int   g_cnt[NN];
__device__ int   g_csrc[NN * SLOT];
__device__ float g_R[NN * 80];     // -5*log2e*( ||h||^2 + ||f||^2 + f2h2 - 2 h@f^T )

// ---------------- f32x2 packed helpers ----------------
__device__ __forceinline__ u64 pk2(float lo, float hi) {
    u64 r; asm("mov.b64 %0,{%1,%2};" : "=l"(r) : "f"(lo), "f"(hi)); return r;
}
__device__ __forceinline__ u64 pk1(float x) {
    u64 r; asm("mov.b64 %0,{%1,%1};" : "=l"(r) : "f"(x)); return r;
}
__device__ __forceinline__ void upk(u64 v, float& lo, float& hi) {
    asm("mov.b64 {%0,%1},%2;" : "=f"(lo), "=f"(hi) : "l"(v));
}
__device__ __forceinline__ u64 fma2(u64 a, u64 b, u64 c) {
    u64 d; asm("fma.rn.f32x2 %0,%1,%2,%3;" : "=l"(d) : "l"(a), "l"(b), "l"(c)); return d;
}
__device__ __forceinline__ u64 mul2(u64 a, u64 b) {
    u64 d; asm("mul.rn.f32x2 %0,%1,%2;" : "=l"(d) : "l"(a), "l"(b)); return d;
}
__device__ __forceinline__ u64 add2(u64 a, u64 b) {
    u64 d; asm("add.rn.f32x2 %0,%1,%2;" : "=l"(d) : "l"(a), "l"(b)); return d;
}
__device__ __forceinline__ float ex2f(float x) {
    float r; asm("ex2.approx.f32 %0,%1;" : "=f"(r) : "f"(x)); return r;
}

// ---------------- bucket fill ----------------
__global__ void k_fill(const int* __restrict__ src, const int* __restrict__ dst) {
    int e = blockIdx.x * blockDim.x + threadIdx.x;
    if (e < EE) {
        int d = dst[e];
        int slot = atomicAdd(&g_cnt[d], 1);
        g_csrc[d * SLOT + slot] = src[e];
    }
}

// ---------------- cp.async helpers ----------------
__device__ __forceinline__ void cp16(uint32_t sdst, const void* gsrc, bool pred) {
    int sz = pred ? 16 : 0;
    asm volatile("cp.async.cg.shared.global [%0], [%1], 16, %2;\n"
                 :: "r"(sdst), "l"(gsrc), "r"(sz));
}
__device__ __forceinline__ void cp_commit() {
    asm volatile("cp.async.commit_group;\n");
}
template <int N>
__device__ __forceinline__ void cp_wait() {
    asm volatile("cp.async.wait_group %0;\n" :: "n"(N));
}

// ---------------- GEMM: oXW = (A[M,K] @ W[K,64]) * rsqrt(cnt+1)  (f32x2-packed, double-buffered) ----------------
#define AS_STRIDE 68
#define AS_TILE  (64 * AS_STRIDE)
#define BS_TILE  (64 * 64)
#define GEMM_SMEM ((2 * AS_TILE + 2 * BS_TILE) * 4)

__global__ __launch_bounds__(128) void k_gemm(
    const float* __restrict__ A, const float* __restrict__ W,
    float* __restrict__ oXW, int M, int K, int lda)
{
    extern __shared__ float smem[];
    float* As = smem;
    float* Bs = smem + 2 * AS_TILE;
    const uint32_t sAs = (uint32_t)__cvta_generic_to_shared(As);
    const uint32_t sBs = (uint32_t)__cvta_generic_to_shared(Bs);

    const int t  = threadIdx.x;
    const int tx = t & 15, ty = t >> 4;
    const int row0 = blockIdx.x * 64;

    u64 accp[8][2];
#pragma unroll
    for (int i = 0; i < 8; i++) { accp[i][0] = 0ull; accp[i][1] = 0ull; }

#pragma unroll
    for (int p = 0; p < 8; p++) {
        int v = t + 128 * p;
        int r = v >> 4, c4 = v & 15;
        int gr = row0 + r;
        cp16(sAs + (r * AS_STRIDE + c4 * 4) * 4,
             A + (size_t)gr * lda + c4 * 4, gr < M);
    }
#pragma unroll
    for (int p = 0; p < 8; p++) {
        int v = t + 128 * p;
        int r = v >> 4, c4 = v & 15;
        cp16(sBs + (r * 64 + c4 * 4) * 4,
             W + (size_t)r * HID + c4 * 4, true);
    }
    cp_commit();

    int buf = 0;
    for (int kt = 0; kt < K; kt += 64, buf ^= 1) {
        if (kt + 64 < K) {
            int nb = buf ^ 1;
#pragma unroll
            for (int p = 0; p < 8; p++) {
                int v = t + 128 * p;
                int r = v >> 4, c4 = v & 15;
                int gr = row0 + r;
                cp16(sAs + (nb * AS_TILE + r * AS_STRIDE + c4 * 4) * 4,
                     A + (size_t)gr * lda + kt + 64 + c4 * 4, gr < M);
            }
#pragma unroll
            for (int p = 0; p < 8; p++) {
                int v = t + 128 * p;
                int r = v >> 4, c4 = v & 15;
                cp16(sBs + (nb * BS_TILE + r * 64 + c4 * 4) * 4,
                     W + (size_t)(kt + 64 + r) * HID + c4 * 4, true);
            }
            cp_commit();
            cp_wait<1>();
        } else {
            cp_wait<0>();
        }
        __syncthreads();

        const float* Ab = As + buf * AS_TILE;
        const float* Bb = Bs + buf * BS_TILE;
#pragma unroll
        for (int k = 0; k < 64; k += 4) {
            float4 a4[8];
            u64 b2[4][2];
#pragma unroll
            for (int i = 0; i < 8; i++) a4[i] = *(const float4*)&Ab[(ty * 8 + i) * AS_STRIDE + k];
#pragma unroll
            for (int kk = 0; kk < 4; kk++) {
                b2[kk][0] = *(const u64*)&Bb[(k + kk) * 64 + tx * 4];
                b2[kk][1] = *(const u64*)&Bb[(k + kk) * 64 + tx * 4 + 2];
            }
#pragma unroll
            for (int i = 0; i < 8; i++) {
                u64 ax = pk1(a4[i].x);
                accp[i][0] = fma2(ax, b2[0][0], accp[i][0]);
                accp[i][1] = fma2(ax, b2[0][1], accp[i][1]);
                u64 ay = pk1(a4[i].y);
                accp[i][0] = fma2(ay, b2[1][0], accp[i][0]);
                accp[i][1] = fma2(ay, b2[1][1], accp[i][1]);
                u64 az = pk1(a4[i].z);
                accp[i][0] = fma2(az, b2[2][0], accp[i][0]);
                accp[i][1] = fma2(az, b2[2][1], accp[i][1]);
                u64 aw = pk1(a4[i].w);
                accp[i][0] = fma2(aw, b2[3][0], accp[i][0]);
                accp[i][1] = fma2(aw, b2[3][1], accp[i][1]);
            }
        }
        __syncthreads();
    }
#pragma unroll
    for (int i = 0; i < 8; i++) {
        int gr = row0 + ty * 8 + i;
        if (gr < M) {
            float dv = rsqrtf((float)g_cnt[gr] + 1.0f);
            float4 o;
            float lo, hi;
            upk(accp[i][0], lo, hi); o.x = lo * dv; o.y = hi * dv;
            upk(accp[i][1], lo, hi); o.z = lo * dv; o.w = hi * dv;
            *(float4*)(oXW + (size_t)gr * HID + tx * 4) = o;
        }
    }
}

// ---------------- gather (float4, MLP 8): h[d] = act( bias + dinv[d]*(xws[d] + sum_in xws[s]) ) ----------------
template <bool RELU>
__global__ __launch_bounds__(256) void k_gather(
    const float4* __restrict__ xws4, const float4* __restrict__ bias4,
    float4* __restrict__ h4)
{
    int d = blockIdx.x * 16 + (threadIdx.x >> 4);
    int f = threadIdx.x & 15;
    int cnt = g_cnt[d];
    const int* lst = g_csrc + (size_t)d * SLOT;
    float4 acc[8];
    acc[0] = xws4[(size_t)d * 16 + f];
#pragma unroll
    for (int j = 1; j < 8; j++) acc[j] = make_float4(0.f, 0.f, 0.f, 0.f);
    int e = 0;
    for (; e + 7 < cnt; e += 8) {
        int s[8];
#pragma unroll
        for (int j = 0; j < 8; j++) s[j] = lst[e + j];
#pragma unroll
        for (int j = 0; j < 8; j++) {
            float4 v = xws4[(size_t)s[j] * 16 + f];
            acc[j].x += v.x; acc[j].y += v.y; acc[j].z += v.z; acc[j].w += v.w;
        }
    }
    for (; e + 1 < cnt; e += 2) {
        int s0 = lst[e], s1 = lst[e + 1];
        float4 v0 = xws4[(size_t)s0 * 16 + f];
        float4 v1 = xws4[(size_t)s1 * 16 + f];
        acc[0].x += v0.x; acc[0].y += v0.y; acc[0].z += v0.z; acc[0].w += v0.w;
        acc[1].x += v1.x; acc[1].y += v1.y; acc[1].z += v1.z; acc[1].w += v1.w;
    }
    if (e < cnt) {
        float4 v = xws4[(size_t)lst[e] * 16 + f];
        acc[0].x += v.x; acc[0].y += v.y; acc[0].z += v.z; acc[0].w += v.w;
    }
#pragma unroll
    for (int j = 1; j < 8; j++) {
        acc[0].x += acc[j].x; acc[0].y += acc[j].y;
        acc[0].z += acc[j].z; acc[0].w += acc[j].w;
    }
    float dv = rsqrtf((float)cnt + 1.0f);
    float4 b = bias4[f];
    float4 o;
    o.x = acc[0].x * dv + b.x;
    o.y = acc[0].y * dv + b.y;
    o.z = acc[0].z * dv + b.z;
    o.w = acc[0].w * dv + b.w;
    if (RELU) {
        o.x = fmaxf(o.x, 0.f); o.y = fmaxf(o.y, 0.f);
        o.z = fmaxf(o.z, 0.f); o.w = fmaxf(o.w, 0.f);
    }
    h4[(size_t)d * 16 + f] = o;
}

// ---------------- R' = -5*log2e*( ||h||^2 + ||f||^2 + f2h2 - 2 h@f^T ) : [NN, 80] ----------------
__global__ __launch_bounds__(256) void k_pr(
    const float* __restrict__ h, const float* __restrict__ tfeat,
    const float* __restrict__ tadj)
{
    __shared__ float hs[64][68];
    __shared__ float tfs[64][81];
    __shared__ float tnl[80];      // ||f||^2 + f2h2 per (tpl,m)
    const int t = threadIdx.x;
    const int r0 = blockIdx.x * 64;
    const float NEG5L = -5.f * 1.4426950408889634f;
#pragma unroll
    for (int p = 0; p < 4; p++) {
        int v = t + 256 * p;
        int r = v >> 4, c4 = v & 15;
        int gr = r0 + r;
        float4 val = make_float4(0.f, 0.f, 0.f, 0.f);
        if (gr < NN) val = *(const float4*)(h + (size_t)gr * HID + c4 * 4);
        *(float4*)&hs[r][c4 * 4] = val;
    }
    for (int q = t; q < 80 * 64; q += 256) {
        int tm = q >> 6, k = q & 63;
        tfs[k][tm] = tfeat[q];
    }
    __syncthreads();
    if (t < 80) {
        float s = 0.f;
#pragma unroll
        for (int k = 0; k < 64; k++) { float v = tfs[k][t]; s += v * v; }
        // f2h2 = (sum_k C2[m,k]^2)/8 for tm = tpl*8+m (templates symmetric)
        float f2 = 0.f;
        const float* c2 = tadj + t * 8;   // tadj[tpl][m][*] at linear offset t*8
#pragma unroll
        for (int k = 0; k < 8; k++) { float c = c2[k]; f2 += c * c; }
        tnl[t] = s + f2 * 0.125f;
    }
    __syncthreads();
    const int ty = t >> 4, tx = t & 15;
    float acc[4][5];
    float h2[4];
#pragma unroll
    for (int i = 0; i < 4; i++) { h2[i] = 0.f;
#pragma unroll
        for (int c = 0; c < 5; c++) acc[i][c] = 0.f; }
#pragma unroll
    for (int k = 0; k < 64; k++) {
        float a[4], b[5];
#pragma unroll
        for (int i = 0; i < 4; i++) a[i] = hs[ty * 4 + i][k];
#pragma unroll
        for (int c = 0; c < 5; c++) b[c] = tfs[k][tx * 5 + c];
#pragma unroll
        for (int i = 0; i < 4; i++) {
            h2[i] += a[i] * a[i];
#pragma unroll
            for (int c = 0; c < 5; c++) acc[i][c] += a[i] * b[c];
        }
    }
#pragma unroll
    for (int i = 0; i < 4; i++) {
        int gr = r0 + ty * 4 + i;
        if (gr < NN) {
#pragma unroll
            for (int c = 0; c < 5; c++)
                g_R[(size_t)gr * 80 + tx * 5 + c] =
                    NEG5L * (h2[i] + tnl[tx * 5 + c] - 2.f * acc[i][c]);
        }
    }
}

// ---------------- FGW distances: split-m (2 threads per node x template), occ 4 ----------------
__global__ __launch_bounds__(160, 4) void k_dist(
    const float* __restrict__ h,
    const int*   __restrict__ nbr_idx,
    const float* __restrict__ nbr_mask,
    const float* __restrict__ C_local,
    const float* __restrict__ tadj,     // [10,8,8]
    const float* __restrict__ Wlin,     // [74,6]
    const float* __restrict__ blin,
    float* __restrict__ out)
{
    __shared__ float C1s[NBD * 81];
    __shared__ u64   C2p[NTPL * 33];    // stride 33 -> distinct banks per template
    __shared__ float h1sh[NBD * 9];
    __shared__ float f1h1[NBD * 9];
    __shared__ float ysh[NBD * NTPL];
    __shared__ int   idxs[NBD * 9];

    const int tid = threadIdx.x;
    const int sub = tid & 1;            // m half: sub*4 .. sub*4+3
    const int pid = tid >> 1;           // 0..79
    const int nl  = pid / 10;
    const int tpl = pid % 10;
    const int node0 = blockIdx.x * NBD;
    const unsigned FULL = 0xffffffffu;

    const float LOG2E = 1.4426950408889634f;

    // ---- cooperative setup ----
    for (int q = tid; q < 320; q += 160) {
        int tt = q >> 5, rem = q & 31;
        C2p[tt * 33 + rem] = pk2(tadj[2 * q], tadj[2 * q + 1]);
    }
    for (int q = tid; q < NBD * 9; q += 160) {
        int nn = q / 9, i = q % 9;
        idxs[nn * 9 + i] = (i == 0) ? (node0 + nn) : nbr_idx[(node0 + nn) * 8 + i - 1];
    }
    for (int q = tid; q < NBD * 81; q += 160)
        C1s[q] = C_local[(size_t)node0 * 81 + q];
    for (int q = tid; q < NBD * 9; q += 160) {
        int nn = q / 9, i = q % 9;
        float s = 0.f;
#pragma unroll
        for (int k = 0; k < 9; k++) s += nbr_mask[(node0 + nn) * 9 + k];
        h1sh[nn * 9 + i] = nbr_mask[(node0 + nn) * 9 + i] / s;
    }
    __syncthreads();
    for (int q = tid; q < NBD * 9; q += 160) {
        int nn = q / 9, i = q % 9;
        float s = 0.f;
#pragma unroll
        for (int k = 0; k < 9; k++) s += C1s[nn * 81 + i * 9 + k] * h1sh[nn * 9 + k];
        f1h1[nn * 9 + i] = s;
    }
    __syncthreads();

    const int c2b = tpl * 33 + 2 * sub;     // this thread's two mp columns at +0, +1
    const u64 NEG5L = pk1(-5.f * LOG2E);
    const u64 CL2   = pk1(10.f * LOG2E);

    // qp[l] = 0.125*sum_k C2[k,m] for local m pairs (rank-1 shortcut, outer 0)
    u64 qp[2];
    {
        const u64 EIGHTH = pk1(0.125f);
#pragma unroll
        for (int l = 0; l < 2; l++) {
            u64 sl = C2p[c2b + l];
#pragma unroll
            for (int k = 1; k < 8; k++) sl = add2(sl, C2p[c2b + k * 4 + l]);
            qp[l] = mul2(sl, EIGHTH);
        }
    }

    float h1r[9];
#pragma unroll
    for (int i = 0; i < 9; i++) h1r[i] = h1sh[nl * 9 + i];

    u64 Tp[18];    // coupling T / A2 (local m half)
    u64 TC[18];    // T @ C2 (local m half)

#pragma unroll 1
    for (int outer = 0; outer < 3; outer++) {
        if (outer == 0) {
            // rank-1: E = f1h1 (x) q -> A2 = ex2(R' + fi5 + CL2*fi*q)
            u64 qC[2] = { mul2(qp[0], CL2), mul2(qp[1], CL2) };
#pragma unroll
            for (int i = 0; i < 9; i++) {
                int id = idxs[nl * 9 + i];
                float4 rq = *(const float4*)(g_R + (size_t)id * 80 + tpl * 8 + 4 * sub);
                u64 rr[2] = { pk2(rq.x, rq.y), pk2(rq.z, rq.w) };
                u64 fi2 = pk1(f1h1[nl * 9 + i]);
                u64 fi5 = mul2(NEG5L, fi2);
#pragma unroll
                for (int l = 0; l < 2; l++) {
                    u64 arg = fma2(fi2, qC[l], add2(rr[l], fi5));
                    float lo, hi; upk(arg, lo, hi);
                    Tp[i * 2 + l] = pk2(ex2f(lo), ex2f(hi));
                }
            }
        } else {
            // TC = T@C2: mirror the other half of T via pair shuffles, k-outer GEMM
#pragma unroll
            for (int i = 0; i < 9; i++) {
                float tl[4], to_[4];
                upk(Tp[i * 2 + 0], tl[0], tl[1]);
                upk(Tp[i * 2 + 1], tl[2], tl[3]);
#pragma unroll
                for (int j = 0; j < 4; j++)
                    to_[j] = __shfl_xor_sync(FULL, tl[j], 1);
                float tv[8];
#pragma unroll
                for (int j = 0; j < 4; j++) {
                    tv[j]     = sub ? to_[j] : tl[j];
                    tv[j + 4] = sub ? tl[j] : to_[j];
                }
                // two-accumulator split over k to halve the dependent chain
                u64 a0a = mul2(pk1(tv[0]), C2p[c2b]);
                u64 a1a = mul2(pk1(tv[0]), C2p[c2b + 1]);
                u64 a0b = mul2(pk1(tv[1]), C2p[c2b + 4]);
                u64 a1b = mul2(pk1(tv[1]), C2p[c2b + 5]);
#pragma unroll
                for (int k = 2; k < 8; k += 2) {
                    u64 ta = pk1(tv[k]);
                    a0a = fma2(ta, C2p[c2b + k * 4], a0a);
                    a1a = fma2(ta, C2p[c2b + k * 4 + 1], a1a);
                    u64 tb = pk1(tv[k + 1]);
                    a0b = fma2(tb, C2p[c2b + (k + 1) * 4], a0b);
                    a1b = fma2(tb, C2p[c2b + (k + 1) * 4 + 1], a1b);
                }
                TC[i * 2 + 0] = add2(a0a, a0b);
                TC[i * 2 + 1] = add2(a1a, a1b);
            }
            // per row: E = C1 @ TC (split chains) ; A2 = ex2(R' + fi5 + CL2*E)
#pragma unroll
            for (int i = 0; i < 9; i++) {
                const float* c1 = C1s + nl * 81 + i * 9;
                u64 ck = pk1(c1[0]);
                u64 e0a = mul2(ck, TC[0]), e1a = mul2(ck, TC[1]);
                ck = pk1(c1[1]);
                u64 e0b = mul2(ck, TC[2]), e1b = mul2(ck, TC[3]);
#pragma unroll
                for (int k = 2; k < 8; k += 2) {
                    u64 ca = pk1(c1[k]);
                    e0a = fma2(ca, TC[k * 2 + 0], e0a);
                    e1a = fma2(ca, TC[k * 2 + 1], e1a);
                    u64 cb = pk1(c1[k + 1]);
                    e0b = fma2(cb, TC[(k + 1) * 2 + 0], e0b);
                    e1b = fma2(cb, TC[(k + 1) * 2 + 1], e1b);
                }
                {
                    u64 c8 = pk1(c1[8]);
                    e0a = fma2(c8, TC[16], e0a);
                    e1a = fma2(c8, TC[17], e1a);
                }
                u64 e0 = add2(e0a, e0b);
                u64 e1 = add2(e1a, e1b);
                int id = idxs[nl * 9 + i];
                float4 rq = *(const float4*)(g_R + (size_t)id * 80 + tpl * 8 + 4 * sub);
                u64 rr[2] = { pk2(rq.x, rq.y), pk2(rq.z, rq.w) };
                u64 fi5 = mul2(NEG5L, pk1(f1h1[nl * 9 + i]));
                u64 ee[2] = { e0, e1 };
#pragma unroll
                for (int l = 0; l < 2; l++) {
                    u64 arg = fma2(CL2, ee[l], add2(rr[l], fi5));
                    float lo, hi; upk(arg, lo, hi);
                    Tp[i * 2 + l] = pk2(ex2f(lo), ex2f(hi));
                }
            }
        }
        // sinkhorn on A2 (=Tp); row sums need the pair's half via 1 shfl
        u64 vp[2] = { pk1(1.f), pk1(1.f) };
        float ui[9];
#pragma unroll 1
        for (int it = 0; it < 5; it++) {
#pragma unroll
            for (int i = 0; i < 9; i++) {
                u64 sp = mul2(Tp[i * 2 + 0], vp[0]);
                sp = fma2(Tp[i * 2 + 1], vp[1], sp);
                float lo, hi; upk(sp, lo, hi);
                float part = lo + hi;
                part += __shfl_xor_sync(FULL, part, 1);
                ui[i] = __fdividef(h1r[i], part + 1e-16f);
            }
            // column sums with two-accumulator split over i
            u64 u0 = pk1(ui[0]);
            u64 sc0a = mul2(u0, Tp[0]), sc1a = mul2(u0, Tp[1]);
            u64 u1 = pk1(ui[1]);
            u64 sc0b = mul2(u1, Tp[2]), sc1b = mul2(u1, Tp[3]);
#pragma unroll
            for (int i = 2; i < 8; i += 2) {
                u64 ua = pk1(ui[i]);
                sc0a = fma2(ua, Tp[i * 2 + 0], sc0a);
                sc1a = fma2(ua, Tp[i * 2 + 1], sc1a);
                u64 ub = pk1(ui[i + 1]);
                sc0b = fma2(ub, Tp[(i + 1) * 2 + 0], sc0b);
                sc1b = fma2(ub, Tp[(i + 1) * 2 + 1], sc1b);
            }
            {
                u64 u8 = pk1(ui[8]);
                sc0a = fma2(u8, Tp[16], sc0a);
                sc1a = fma2(u8, Tp[17], sc1a);
            }
            u64 sc0 = add2(sc0a, sc0b);
            u64 sc1 = add2(sc1a, sc1b);
            {
                float lo, hi; upk(sc0, lo, hi);
                vp[0] = pk2(__fdividef(0.125f, lo + 1e-16f),
                            __fdividef(0.125f, hi + 1e-16f));
                upk(sc1, lo, hi);
                vp[1] = pk2(__fdividef(0.125f, lo + 1e-16f),
                            __fdividef(0.125f, hi + 1e-16f));
            }
        }
        // T = u * A2 * v
#pragma unroll
        for (int i = 0; i < 9; i++) {
            u64 u2 = pk1(ui[i]);
            Tp[i * 2 + 0] = mul2(mul2(u2, Tp[i * 2 + 0]), vp[0]);
            Tp[i * 2 + 1] = mul2(mul2(u2, Tp[i * 2 + 1]), vp[1]);
        }
    }

    // ---- final objective: obj = (-0.1*ln2)*sum(T∘S) - sum((C1^T@T)∘(T@C2)), S = R'+fi5 ----
    u64 accS = pk1(0.f);
#pragma unroll
    for (int i = 0; i < 9; i++) {
        int id = idxs[nl * 9 + i];
        float4 rq = *(const float4*)(g_R + (size_t)id * 80 + tpl * 8 + 4 * sub);
        u64 rr[2] = { pk2(rq.x, rq.y), pk2(rq.z, rq.w) };
        u64 fi5 = mul2(NEG5L, pk1(f1h1[nl * 9 + i]));
#pragma unroll
        for (int l = 0; l < 2; l++) {
            u64 sp = add2(rr[l], fi5);
            accS = fma2(Tp[i * 2 + l], sp, accS);
        }
    }
    // TC = T@C2 (mirror + k-outer)
#pragma unroll
    for (int i = 0; i < 9; i++) {
        float tl[4], to_[4];
        upk(Tp[i * 2 + 0], tl[0], tl[1]);
        upk(Tp[i * 2 + 1], tl[2], tl[3]);
#pragma unroll
        for (int j = 0; j < 4; j++)
            to_[j] = __shfl_xor_sync(FULL, tl[j], 1);
        float tv[8];
#pragma unroll
        for (int j = 0; j < 4; j++) {
            tv[j]     = sub ? to_[j] : tl[j];
            tv[j + 4] = sub ? tl[j] : to_[j];
        }
        u64 a0 = mul2(pk1(tv[0]), C2p[c2b]);
        u64 a1 = mul2(pk1(tv[0]), C2p[c2b + 1]);
#pragma unroll
        for (int k = 1; k < 8; k++) {
            u64 t2 = pk1(tv[k]);
            a0 = fma2(t2, C2p[c2b + k * 4], a0);
            a1 = fma2(t2, C2p[c2b + k * 4 + 1], a1);
        }
        TC[i * 2 + 0] = a0;
        TC[i * 2 + 1] = a1;
    }
    // accE = sum_k (C1^T@T)[k] . TC[k]  (V rows on the fly, local m)
    u64 accE = pk1(0.f);
#pragma unroll
    for (int k = 0; k < 9; k++) {
        const float* c1 = C1s + nl * 81 + k;    // column k, stride 9
        u64 ck = pk1(c1[0]);
        u64 v0 = mul2(ck, Tp[0]), v1 = mul2(ck, Tp[1]);
#pragma unroll
        for (int i = 1; i < 9; i++) {
            ck = pk1(c1[i * 9]);
            v0 = fma2(ck, Tp[i * 2 + 0], v0);
            v1 = fma2(ck, Tp[i * 2 + 1], v1);
        }
        accE = fma2(v0, TC[k * 2 + 0], accE);
        accE = fma2(v1, TC[k * 2 + 1], accE);
    }
    {
        float slo, shi, elo, ehi;
        upk(accS, slo, shi); upk(accE, elo, ehi);
        float val = -0.06931471805599453f * (slo + shi) - (elo + ehi);
        val += __shfl_xor_sync(FULL, val, 1);
        if (sub == 0) ysh[nl * 10 + tpl] = val;
    }
    __syncthreads();

    // head: out = relu(concat(h, y) @ Wlin + blin)
    if (tid < NBD * NCLS) {
        int nn = tid / NCLS, c = tid % NCLS;
        float acc = blin[c];
#pragma unroll 8
        for (int k = 0; k < HID; k++)
            acc += h[(size_t)(node0 + nn) * HID + k] * Wlin[k * NCLS + c];
#pragma unroll
        for (int t = 0; t < NTPL; t++)
            acc += ysh[nn * 10 + t] * Wlin[(HID + t) * NCLS + c];
        out[(node0 + nn) * NCLS + c] = fmaxf(acc, 0.f);
    }
}

// ---------------- launch ----------------
extern "C" void kernel_launch(void* const* d_in, const int* in_sizes, int n_in,
                              void* d_out, int out_size)
{
    const float* x     = (const float*)d_in[0];
    const int*   ei    = (const int*)  d_in[1];
    const int*   nbr   = (const int*)  d_in[2];
    const float* mask  = (const float*)d_in[3];
    const float* Cl    = (const float*)d_in[4];
    const float* W1    = (const float*)d_in[5];
    const float* b1    = (const float*)d_in[6];
    const float* W2    = (const float*)d_in[7];
    const float* b2    = (const float*)d_in[8];
    const float* tadj  = (const float*)d_in[9];
    const float* tfeat = (const float*)d_in[10];
    const float* Wlin  = (const float*)d_in[11];
    const float* blin  = (const float*)d_in[12];
    float* out = (float*)d_out;

    const int* src = ei;
    const int* dst = ei + EE;

    void *pA, *pB, *pC, *pCnt;
    cudaGetSymbolAddress(&pA, g_bufA);
    cudaGetSymbolAddress(&pB, g_bufB);
    cudaGetSymbolAddress(&pC, g_bufC);
    cudaGetSymbolAddress(&pCnt, g_cnt);
    float* bufA = (float*)pA;
    float* bufB = (float*)pB;
    float* bufC = (float*)pC;

    cudaFuncSetAttribute(k_gemm, cudaFuncAttributeMaxDynamicSharedMemorySize, GEMM_SMEM);

    cudaMemsetAsync(pCnt, 0, NN * sizeof(int));
    k_fill<<<(EE + 255) / 256, 256>>>(src, dst);

    k_gemm<<<(NN + 63) / 64, 128, GEMM_SMEM>>>(x, W1, bufA, NN, FIN, FIN);
    k_gather<true><<<NN / 16, 256>>>((const float4*)bufA, (const float4*)b1, (float4*)bufB);

    k_gemm<<<(NN + 63) / 64, 128, GEMM_SMEM>>>(bufB, W2, bufA, NN, HID, HID);
    k_gather<false><<<NN / 16, 256>>>((const float4*)bufA, (const float4*)b2, (float4*)bufC);

    k_pr<<<(NN + 63) / 64, 256>>>(bufC, tfeat, tadj);

    k_dist<<<NN / NBD, 160>>>(bufC, nbr, mask, Cl, tadj, Wlin, blin, out);
}

// round 16
// speedup vs baseline: 1.0829x; 1.0318x over previous
#include <cuda_runtime.h>
#include <cstdint>

#define NN   20000
#define EE   320000
#define FIN  512
#define HID  64
#define LL   9
#define NTPL 10
#define NTN  8
#define NCLS 6
#define NBD  8       // nodes per k_dist block
#define SLOT 64      // max in-degree bucket

typedef unsigned long long u64;

// -------- scratch (no cudaMalloc allowed) --------
__device__ float g_bufA[NN * HID];
__device__ float g_bufB[NN * HID];
__device__ float g_bufC[NN * HID];
__device__ int   g_cnt[NN];        // zero-initialized at load; re-zeroed by k_pr each launch
__device__ int   g_csrc[NN * SLOT];
__device__ float g_R[NN * 80];     // -5*log2e*( ||h||^2 + ||f||^2 + f2h2 - 2 h@f^T )

// ---------------- f32x2 packed helpers ----------------
__device__ __forceinline__ u64 pk2(float lo, float hi) {
    u64 r; asm("mov.b64 %0,{%1,%2};" : "=l"(r) : "f"(lo), "f"(hi)); return r;
}
__device__ __forceinline__ u64 pk1(float x) {
    u64 r; asm("mov.b64 %0,{%1,%1};" : "=l"(r) : "f"(x)); return r;
}
__device__ __forceinline__ void upk(u64 v, float& lo, float& hi) {
    asm("mov.b64 {%0,%1},%2;" : "=f"(lo), "=f"(hi) : "l"(v));
}
__device__ __forceinline__ u64 fma2(u64 a, u64 b, u64 c) {
    u64 d; asm("fma.rn.f32x2 %0,%1,%2,%3;" : "=l"(d) : "l"(a), "l"(b), "l"(c)); return d;
}
__device__ __forceinline__ u64 mul2(u64 a, u64 b) {
    u64 d; asm("mul.rn.f32x2 %0,%1,%2;" : "=l"(d) : "l"(a), "l"(b)); return d;
}
__device__ __forceinline__ u64 add2(u64 a, u64 b) {
    u64 d; asm("add.rn.f32x2 %0,%1,%2;" : "=l"(d) : "l"(a), "l"(b)); return d;
}
__device__ __forceinline__ float ex2f(float x) {
    float r; asm("ex2.approx.f32 %0,%1;" : "=f"(r) : "f"(x)); return r;
}

// ---------------- bucket fill ----------------
__global__ void k_fill(const int* __restrict__ src, const int* __restrict__ dst) {
    int e = blockIdx.x * blockDim.x + threadIdx.x;
    if (e < EE) {
        int d = dst[e];
        int slot = atomicAdd(&g_cnt[d], 1);
        g_csrc[d * SLOT + slot] = src[e];
    }
}

// ---------------- cp.async helpers ----------------
__device__ __forceinline__ void cp16(uint32_t sdst, const void* gsrc, bool pred) {
    int sz = pred ? 16 : 0;
    asm volatile("cp.async.cg.shared.global [%0], [%1], 16, %2;\n"
                 :: "r"(sdst), "l"(gsrc), "r"(sz));
}
__device__ __forceinline__ void cp_commit() {
    asm volatile("cp.async.commit_group;\n");
}
template <int N>
__device__ __forceinline__ void cp_wait() {
    asm volatile("cp.async.wait_group %0;\n" :: "n"(N));
}

// ---------------- GEMM: oXW = (A[M,K] @ W[K,64]) * rsqrt(cnt+1)  (f32x2-packed, double-buffered) ----------------
#define AS_STRIDE 68
#define AS_TILE  (64 * AS_STRIDE)
#define BS_TILE  (64 * 64)
#define GEMM_SMEM ((2 * AS_TILE + 2 * BS_TILE) * 4)

__global__ __launch_bounds__(128) void k_gemm(
    const float* __restrict__ A, const float* __restrict__ W,
    float* __restrict__ oXW, int M, int K, int lda)
{
    extern __shared__ float smem[];
    float* As = smem;
    float* Bs = smem + 2 * AS_TILE;
    const uint32_t sAs = (uint32_t)__cvta_generic_to_shared(As);
    const uint32_t sBs = (uint32_t)__cvta_generic_to_shared(Bs);

    const int t  = threadIdx.x;
    const int tx = t & 15, ty = t >> 4;
    const int row0 = blockIdx.x * 64;

    u64 accp[8][2];
#pragma unroll
    for (int i = 0; i < 8; i++) { accp[i][0] = 0ull; accp[i][1] = 0ull; }

#pragma unroll
    for (int p = 0; p < 8; p++) {
        int v = t + 128 * p;
        int r = v >> 4, c4 = v & 15;
        int gr = row0 + r;
        cp16(sAs + (r * AS_STRIDE + c4 * 4) * 4,
             A + (size_t)gr * lda + c4 * 4, gr < M);
    }
#pragma unroll
    for (int p = 0; p < 8; p++) {
        int v = t + 128 * p;
        int r = v >> 4, c4 = v & 15;
        cp16(sBs + (r * 64 + c4 * 4) * 4,
             W + (size_t)r * HID + c4 * 4, true);
    }
    cp_commit();

    int buf = 0;
    for (int kt = 0; kt < K; kt += 64, buf ^= 1) {
        if (kt + 64 < K) {
            int nb = buf ^ 1;
#pragma unroll
            for (int p = 0; p < 8; p++) {
                int v = t + 128 * p;
                int r = v >> 4, c4 = v & 15;
                int gr = row0 + r;
                cp16(sAs + (nb * AS_TILE + r * AS_STRIDE + c4 * 4) * 4,
                     A + (size_t)gr * lda + kt + 64 + c4 * 4, gr < M);
            }
#pragma unroll
            for (int p = 0; p < 8; p++) {
                int v = t + 128 * p;
                int r = v >> 4, c4 = v & 15;
                cp16(sBs + (nb * BS_TILE + r * 64 + c4 * 4) * 4,
                     W + (size_t)(kt + 64 + r) * HID + c4 * 4, true);
            }
            cp_commit();
            cp_wait<1>();
        } else {
            cp_wait<0>();
        }
        __syncthreads();

        const float* Ab = As + buf * AS_TILE;
        const float* Bb = Bs + buf * BS_TILE;
#pragma unroll
        for (int k = 0; k < 64; k += 4) {
            float4 a4[8];
            u64 b2[4][2];
#pragma unroll
            for (int i = 0; i < 8; i++) a4[i] = *(const float4*)&Ab[(ty * 8 + i) * AS_STRIDE + k];
#pragma unroll
            for (int kk = 0; kk < 4; kk++) {
                b2[kk][0] = *(const u64*)&Bb[(k + kk) * 64 + tx * 4];
                b2[kk][1] = *(const u64*)&Bb[(k + kk) * 64 + tx * 4 + 2];
            }
#pragma unroll
            for (int i = 0; i < 8; i++) {
                u64 ax = pk1(a4[i].x);
                accp[i][0] = fma2(ax, b2[0][0], accp[i][0]);
                accp[i][1] = fma2(ax, b2[0][1], accp[i][1]);
                u64 ay = pk1(a4[i].y);
                accp[i][0] = fma2(ay, b2[1][0], accp[i][0]);
                accp[i][1] = fma2(ay, b2[1][1], accp[i][1]);
                u64 az = pk1(a4[i].z);
                accp[i][0] = fma2(az, b2[2][0], accp[i][0]);
                accp[i][1] = fma2(az, b2[2][1], accp[i][1]);
                u64 aw = pk1(a4[i].w);
                accp[i][0] = fma2(aw, b2[3][0], accp[i][0]);
                accp[i][1] = fma2(aw, b2[3][1], accp[i][1]);
            }
        }
        __syncthreads();
    }
#pragma unroll
    for (int i = 0; i < 8; i++) {
        int gr = row0 + ty * 8 + i;
        if (gr < M) {
            float dv = rsqrtf((float)g_cnt[gr] + 1.0f);
            float4 o;
            float lo, hi;
            upk(accp[i][0], lo, hi); o.x = lo * dv; o.y = hi * dv;
            upk(accp[i][1], lo, hi); o.z = lo * dv; o.w = hi * dv;
            *(float4*)(oXW + (size_t)gr * HID + tx * 4) = o;
        }
    }
}

// ---------------- gather (float4, MLP 6, 5 blocks/SM): h[d] = act( bias + dinv*(xws[d] + sum_in xws[s]) ) ----------------
template <bool RELU>
__global__ __launch_bounds__(256, 5) void k_gather(
    const float4* __restrict__ xws4, const float4* __restrict__ bias4,
    float4* __restrict__ h4)
{
    int d = blockIdx.x * 16 + (threadIdx.x >> 4);
    int f = threadIdx.x & 15;
    int cnt = g_cnt[d];
    const int* lst = g_csrc + (size_t)d * SLOT;
    float4 acc[6];
    acc[0] = xws4[(size_t)d * 16 + f];
#pragma unroll
    for (int j = 1; j < 6; j++) acc[j] = make_float4(0.f, 0.f, 0.f, 0.f);
    int e = 0;
    for (; e + 5 < cnt; e += 6) {
        int s[6];
#pragma unroll
        for (int j = 0; j < 6; j++) s[j] = lst[e + j];
#pragma unroll
        for (int j = 0; j < 6; j++) {
            float4 v = xws4[(size_t)s[j] * 16 + f];
            acc[j].x += v.x; acc[j].y += v.y; acc[j].z += v.z; acc[j].w += v.w;
        }
    }
    for (; e + 1 < cnt; e += 2) {
        int s0 = lst[e], s1 = lst[e + 1];
        float4 v0 = xws4[(size_t)s0 * 16 + f];
        float4 v1 = xws4[(size_t)s1 * 16 + f];
        acc[0].x += v0.x; acc[0].y += v0.y; acc[0].z += v0.z; acc[0].w += v0.w;
        acc[1].x += v1.x; acc[1].y += v1.y; acc[1].z += v1.z; acc[1].w += v1.w;
    }
    if (e < cnt) {
        float4 v = xws4[(size_t)lst[e] * 16 + f];
        acc[0].x += v.x; acc[0].y += v.y; acc[0].z += v.z; acc[0].w += v.w;
    }
#pragma unroll
    for (int j = 1; j < 6; j++) {
        acc[0].x += acc[j].x; acc[0].y += acc[j].y;
        acc[0].z += acc[j].z; acc[0].w += acc[j].w;
    }
    float dv = rsqrtf((float)cnt + 1.0f);
    float4 b = bias4[f];
    float4 o;
    o.x = acc[0].x * dv + b.x;
    o.y = acc[0].y * dv + b.y;
    o.z = acc[0].z * dv + b.z;
    o.w = acc[0].w * dv + b.w;
    if (RELU) {
        o.x = fmaxf(o.x, 0.f); o.y = fmaxf(o.y, 0.f);
        o.z = fmaxf(o.z, 0.f); o.w = fmaxf(o.w, 0.f);
    }
    h4[(size_t)d * 16 + f] = o;
}

// ---------------- R' = -5*log2e*( ||h||^2 + ||f||^2 + f2h2 - 2 h@f^T ) + g_cnt reset ----------------
__global__ __launch_bounds__(256) void k_pr(
    const float* __restrict__ h, const float* __restrict__ tfeat,
    const float* __restrict__ tadj)
{
    __shared__ float hs[64][68];
    __shared__ float tfs[64][81];
    __shared__ float tnl[80];      // ||f||^2 + f2h2 per (tpl,m)
    const int t = threadIdx.x;
    const int r0 = blockIdx.x * 64;
    const float NEG5L = -5.f * 1.4426950408889634f;
#pragma unroll
    for (int p = 0; p < 4; p++) {
        int v = t + 256 * p;
        int r = v >> 4, c4 = v & 15;
        int gr = r0 + r;
        float4 val = make_float4(0.f, 0.f, 0.f, 0.f);
        if (gr < NN) val = *(const float4*)(h + (size_t)gr * HID + c4 * 4);
        *(float4*)&hs[r][c4 * 4] = val;
    }
    for (int q = t; q < 80 * 64; q += 256) {
        int tm = q >> 6, k = q & 63;
        tfs[k][tm] = tfeat[q];
    }
    // reset g_cnt for the next launch (all consumers of g_cnt have already run)
    if (t < 64 && r0 + t < NN) g_cnt[r0 + t] = 0;
    __syncthreads();
    if (t < 80) {
        float s = 0.f;
#pragma unroll
        for (int k = 0; k < 64; k++) { float v = tfs[k][t]; s += v * v; }
        float f2 = 0.f;
        const float* c2 = tadj + t * 8;   // templates symmetric: row m == col m
#pragma unroll
        for (int k = 0; k < 8; k++) { float c = c2[k]; f2 += c * c; }
        tnl[t] = s + f2 * 0.125f;
    }
    __syncthreads();
    const int ty = t >> 4, tx = t & 15;
    float acc[4][5];
    float h2[4];
#pragma unroll
    for (int i = 0; i < 4; i++) { h2[i] = 0.f;
#pragma unroll
        for (int c = 0; c < 5; c++) acc[i][c] = 0.f; }
#pragma unroll
    for (int k = 0; k < 64; k++) {
        float a[4], b[5];
#pragma unroll
        for (int i = 0; i < 4; i++) a[i] = hs[ty * 4 + i][k];
#pragma unroll
        for (int c = 0; c < 5; c++) b[c] = tfs[k][tx * 5 + c];
#pragma unroll
        for (int i = 0; i < 4; i++) {
            h2[i] += a[i] * a[i];
#pragma unroll
            for (int c = 0; c < 5; c++) acc[i][c] += a[i] * b[c];
        }
    }
#pragma unroll
    for (int i = 0; i < 4; i++) {
        int gr = r0 + ty * 4 + i;
        if (gr < NN) {
#pragma unroll
            for (int c = 0; c < 5; c++)
                g_R[(size_t)gr * 80 + tx * 5 + c] =
                    NEG5L * (h2[i] + tnl[tx * 5 + c] - 2.f * acc[i][c]);
        }
    }
}

// ---------------- FGW distances: split-m (2 threads per node x template), occ 4 ----------------
__global__ __launch_bounds__(160, 4) void k_dist(
    const float* __restrict__ h,
    const int*   __restrict__ nbr_idx,
    const float* __restrict__ nbr_mask,
    const float* __restrict__ C_local,
    const float* __restrict__ tadj,     // [10,8,8]
    const float* __restrict__ Wlin,     // [74,6]
    const float* __restrict__ blin,
    float* __restrict__ out)
{
    __shared__ float C1s[NBD * 81];
    __shared__ u64   C2p[NTPL * 33];    // stride 33 -> distinct banks per template
    __shared__ float h1sh[NBD * 9];
    __shared__ float f1h1[NBD * 9];
    __shared__ float ysh[NBD * NTPL];
    __shared__ int   idxs[NBD * 9];

    const int tid = threadIdx.x;
    const int sub = tid & 1;            // m half: sub*4 .. sub*4+3
    const int pid = tid >> 1;           // 0..79
    const int nl  = pid / 10;
    const int tpl = pid % 10;
    const int node0 = blockIdx.x * NBD;
    const unsigned FULL = 0xffffffffu;

    const float LOG2E = 1.4426950408889634f;

    // ---- cooperative setup ----
    for (int q = tid; q < 320; q += 160) {
        int tt = q >> 5, rem = q & 31;
        C2p[tt * 33 + rem] = pk2(tadj[2 * q], tadj[2 * q + 1]);
    }
    for (int q = tid; q < NBD * 9; q += 160) {
        int nn = q / 9, i = q % 9;
        idxs[nn * 9 + i] = (i == 0) ? (node0 + nn) : nbr_idx[(node0 + nn) * 8 + i - 1];
    }
    for (int q = tid; q < NBD * 81; q += 160)
        C1s[q] = C_local[(size_t)node0 * 81 + q];
    for (int q = tid; q < NBD * 9; q += 160) {
        int nn = q / 9, i = q % 9;
        float s = 0.f;
#pragma unroll
        for (int k = 0; k < 9; k++) s += nbr_mask[(node0 + nn) * 9 + k];
        h1sh[nn * 9 + i] = nbr_mask[(node0 + nn) * 9 + i] / s;
    }
    __syncthreads();
    for (int q = tid; q < NBD * 9; q += 160) {
        int nn = q / 9, i = q % 9;
        float s = 0.f;
#pragma unroll
        for (int k = 0; k < 9; k++) s += C1s[nn * 81 + i * 9 + k] * h1sh[nn * 9 + k];
        f1h1[nn * 9 + i] = s;
    }
    __syncthreads();

    const int c2b = tpl * 33 + 2 * sub;     // this thread's two mp columns at +0, +1
    const u64 NEG5L = pk1(-5.f * LOG2E);
    const u64 CL2   = pk1(10.f * LOG2E);

    // qp[l] = 0.125*sum_k C2[k,m] for local m pairs (rank-1 shortcut, outer 0)
    u64 qp[2];
    {
        const u64 EIGHTH = pk1(0.125f);
#pragma unroll
        for (int l = 0; l < 2; l++) {
            u64 sl = C2p[c2b + l];
#pragma unroll
            for (int k = 1; k < 8; k++) sl = add2(sl, C2p[c2b + k * 4 + l]);
            qp[l] = mul2(sl, EIGHTH);
        }
    }

    float h1r[9];
#pragma unroll
    for (int i = 0; i < 9; i++) h1r[i] = h1sh[nl * 9 + i];

    u64 Tp[18];    // coupling T / A2 (local m half)
    u64 TC[18];    // T @ C2 (local m half)

#pragma unroll 1
    for (int outer = 0; outer < 3; outer++) {
        if (outer == 0) {
            // rank-1: E = f1h1 (x) q -> A2 = ex2(R' + fi5 + CL2*fi*q)
            u64 qC[2] = { mul2(qp[0], CL2), mul2(qp[1], CL2) };
#pragma unroll
            for (int i = 0; i < 9; i++) {
                int id = idxs[nl * 9 + i];
                float4 rq = *(const float4*)(g_R + (size_t)id * 80 + tpl * 8 + 4 * sub);
                u64 rr[2] = { pk2(rq.x, rq.y), pk2(rq.z, rq.w) };
                u64 fi2 = pk1(f1h1[nl * 9 + i]);
                u64 fi5 = mul2(NEG5L, fi2);
#pragma unroll
                for (int l = 0; l < 2; l++) {
                    u64 arg = fma2(fi2, qC[l], add2(rr[l], fi5));
                    float lo, hi; upk(arg, lo, hi);
                    Tp[i * 2 + l] = pk2(ex2f(lo), ex2f(hi));
                }
            }
        } else {
            // TC = T@C2: mirror the other half of T via pair shuffles, k-outer GEMM
#pragma unroll
            for (int i = 0; i < 9; i++) {
                float tl[4], to_[4];
                upk(Tp[i * 2 + 0], tl[0], tl[1]);
                upk(Tp[i * 2 + 1], tl[2], tl[3]);
#pragma unroll
                for (int j = 0; j < 4; j++)
                    to_[j] = __shfl_xor_sync(FULL, tl[j], 1);
                float tv[8];
#pragma unroll
                for (int j = 0; j < 4; j++) {
                    tv[j]     = sub ? to_[j] : tl[j];
                    tv[j + 4] = sub ? tl[j] : to_[j];
                }
                // two-accumulator split over k to halve the dependent chain
                u64 a0a = mul2(pk1(tv[0]), C2p[c2b]);
                u64 a1a = mul2(pk1(tv[0]), C2p[c2b + 1]);
                u64 a0b = mul2(pk1(tv[1]), C2p[c2b + 4]);
                u64 a1b = mul2(pk1(tv[1]), C2p[c2b + 5]);
#pragma unroll
                for (int k = 2; k < 8; k += 2) {
                    u64 ta = pk1(tv[k]);
                    a0a = fma2(ta, C2p[c2b + k * 4], a0a);
                    a1a = fma2(ta, C2p[c2b + k * 4 + 1], a1a);
                    u64 tb = pk1(tv[k + 1]);
                    a0b = fma2(tb, C2p[c2b + (k + 1) * 4], a0b);
                    a1b = fma2(tb, C2p[c2b + (k + 1) * 4 + 1], a1b);
                }
                TC[i * 2 + 0] = add2(a0a, a0b);
                TC[i * 2 + 1] = add2(a1a, a1b);
            }
            // per row: E = C1 @ TC (split chains) ; A2 = ex2(R' + fi5 + CL2*E)
#pragma unroll
            for (int i = 0; i < 9; i++) {
                const float* c1 = C1s + nl * 81 + i * 9;
                u64 ck = pk1(c1[0]);
                u64 e0a = mul2(ck, TC[0]), e1a = mul2(ck, TC[1]);
                ck = pk1(c1[1]);
                u64 e0b = mul2(ck, TC[2]), e1b = mul2(ck, TC[3]);
#pragma unroll
                for (int k = 2; k < 8; k += 2) {
                    u64 ca = pk1(c1[k]);
                    e0a = fma2(ca, TC[k * 2 + 0], e0a);
                    e1a = fma2(ca, TC[k * 2 + 1], e1a);
                    u64 cb = pk1(c1[k + 1]);
                    e0b = fma2(cb, TC[(k + 1) * 2 + 0], e0b);
                    e1b = fma2(cb, TC[(k + 1) * 2 + 1], e1b);
                }
                {
                    u64 c8 = pk1(c1[8]);
                    e0a = fma2(c8, TC[16], e0a);
                    e1a = fma2(c8, TC[17], e1a);
                }
                u64 e0 = add2(e0a, e0b);
                u64 e1 = add2(e1a, e1b);
                int id = idxs[nl * 9 + i];
                float4 rq = *(const float4*)(g_R + (size_t)id * 80 + tpl * 8 + 4 * sub);
                u64 rr[2] = { pk2(rq.x, rq.y), pk2(rq.z, rq.w) };
                u64 fi5 = mul2(NEG5L, pk1(f1h1[nl * 9 + i]));
                u64 ee[2] = { e0, e1 };
#pragma unroll
                for (int l = 0; l < 2; l++) {
                    u64 arg = fma2(CL2, ee[l], add2(rr[l], fi5));
                    float lo, hi; upk(arg, lo, hi);
                    Tp[i * 2 + l] = pk2(ex2f(lo), ex2f(hi));
                }
            }
        }
        // sinkhorn on A2 (=Tp); row sums need the pair's half via 1 shfl
        u64 vp[2] = { pk1(1.f), pk1(1.f) };
        float ui[9];
#pragma unroll 1
        for (int it = 0; it < 5; it++) {
#pragma unroll
            for (int i = 0; i < 9; i++) {
                u64 sp = mul2(Tp[i * 2 + 0], vp[0]);
                sp = fma2(Tp[i * 2 + 1], vp[1], sp);
                float lo, hi; upk(sp, lo, hi);
                float part = lo + hi;
                part += __shfl_xor_sync(FULL, part, 1);
                ui[i] = __fdividef(h1r[i], part + 1e-16f);
            }
            // column sums with two-accumulator split over i
            u64 u0 = pk1(ui[0]);
            u64 sc0a = mul2(u0, Tp[0]), sc1a = mul2(u0, Tp[1]);
            u64 u1 = pk1(ui[1]);
            u64 sc0b = mul2(u1, Tp[2]), sc1b = mul2(u1, Tp[3]);
#pragma unroll
            for (int i = 2; i < 8; i += 2) {
                u64 ua = pk1(ui[i]);
                sc0a = fma2(ua, Tp[i * 2 + 0], sc0a);
                sc1a = fma2(ua, Tp[i * 2 + 1], sc1a);
                u64 ub = pk1(ui[i + 1]);
                sc0b = fma2(ub, Tp[(i + 1) * 2 + 0], sc0b);
                sc1b = fma2(ub, Tp[(i + 1) * 2 + 1], sc1b);
            }
            {
                u64 u8 = pk1(ui[8]);
                sc0a = fma2(u8, Tp[16], sc0a);
                sc1a = fma2(u8, Tp[17], sc1a);
            }
            u64 sc0 = add2(sc0a, sc0b);
            u64 sc1 = add2(sc1a, sc1b);
            {
                float lo, hi; upk(sc0, lo, hi);
                vp[0] = pk2(__fdividef(0.125f, lo + 1e-16f),
                            __fdividef(0.125f, hi + 1e-16f));
                upk(sc1, lo, hi);
                vp[1] = pk2(__fdividef(0.125f, lo + 1e-16f),
                            __fdividef(0.125f, hi + 1e-16f));
            }
        }
        // T = u * A2 * v
#pragma unroll
        for (int i = 0; i < 9; i++) {
            u64 u2 = pk1(ui[i]);
            Tp[i * 2 + 0] = mul2(mul2(u2, Tp[i * 2 + 0]), vp[0]);
            Tp[i * 2 + 1] = mul2(mul2(u2, Tp[i * 2 + 1]), vp[1]);
        }
    }

    // ---- final objective: obj = (-0.1*ln2)*sum(T∘S) - sum((C1^T@T)∘(T@C2)), S = R'+fi5 ----
    u64 accS = pk1(0.f);
#pragma unroll
    for (int i = 0; i < 9; i++) {
        int id = idxs[nl * 9 + i];
        float4 rq = *(const float4*)(g_R + (size_t)id * 80 + tpl * 8 + 4 * sub);
        u64 rr[2] = { pk2(rq.x, rq.y), pk2(rq.z, rq.w) };
        u64 fi5 = mul2(NEG5L, pk1(f1h1[nl * 9 + i]));
#pragma unroll
        for (int l = 0; l < 2; l++) {
            u64 sp = add2(rr[l], fi5);
            accS = fma2(Tp[i * 2 + l], sp, accS);
        }
    }
    // TC = T@C2 (mirror + k-outer)
#pragma unroll
    for (int i = 0; i < 9; i++) {
        float tl[4], to_[4];
        upk(Tp[i * 2 + 0], tl[0], tl[1]);
        upk(Tp[i * 2 + 1], tl[2], tl[3]);
#pragma unroll
        for (int j = 0; j < 4; j++)
            to_[j] = __shfl_xor_sync(FULL, tl[j], 1);
        float tv[8];
#pragma unroll
        for (int j = 0; j < 4; j++) {
            tv[j]     = sub ? to_[j] : tl[j];
            tv[j + 4] = sub ? tl[j] : to_[j];
        }
        u64 a0 = mul2(pk1(tv[0]), C2p[c2b]);
        u64 a1 = mul2(pk1(tv[0]), C2p[c2b + 1]);
#pragma unroll
        for (int k = 1; k < 8; k++) {
            u64 t2 = pk1(tv[k]);
            a0 = fma2(t2, C2p[c2b + k * 4], a0);
            a1 = fma2(t2, C2p[c2b + k * 4 + 1], a1);
        }
        TC[i * 2 + 0] = a0;
        TC[i * 2 + 1] = a1;
    }
    // accE = sum_k (C1^T@T)[k] . TC[k]  (V rows on the fly, local m)
    u64 accE = pk1(0.f);
#pragma unroll
    for (int k = 0; k < 9; k++) {
        const float* c1 = C1s + nl * 81 + k;    // column k, stride 9
        u64 ck = pk1(c1[0]);
        u64 v0 = mul2(ck, Tp[0]), v1 = mul2(ck, Tp[1]);
#pragma unroll
        for (int i = 1; i < 9; i++) {
            ck = pk1(c1[i * 9]);
            v0 = fma2(ck, Tp[i * 2 + 0], v0);
            v1 = fma2(ck, Tp[i * 2 + 1], v1);
        }
        accE = fma2(v0, TC[k * 2 + 0], accE);
        accE = fma2(v1, TC[k * 2 + 1], accE);
    }
    {
        float slo, shi, elo, ehi;
        upk(accS, slo, shi); upk(accE, elo, ehi);
        float val = -0.06931471805599453f * (slo + shi) - (elo + ehi);
        val += __shfl_xor_sync(FULL, val, 1);
        if (sub == 0) ysh[nl * 10 + tpl] = val;
    }
    __syncthreads();

    // head: out = relu(concat(h, y) @ Wlin + blin)
    if (tid < NBD * NCLS) {
        int nn = tid / NCLS, c = tid % NCLS;
        float acc = blin[c];
#pragma unroll 8
        for (int k = 0; k < HID; k++)
            acc += h[(size_t)(node0 + nn) * HID + k] * Wlin[k * NCLS + c];
#pragma unroll
        for (int t = 0; t < NTPL; t++)
            acc += ysh[nn * 10 + t] * Wlin[(HID + t) * NCLS + c];
        out[(node0 + nn) * NCLS + c] = fmaxf(acc, 0.f);
    }
}

// ---------------- launch ----------------
extern "C" void kernel_launch(void* const* d_in, const int* in_sizes, int n_in,
                              void* d_out, int out_size)
{
    const float* x     = (const float*)d_in[0];
    const int*   ei    = (const int*)  d_in[1];
    const int*   nbr   = (const int*)  d_in[2];
    const float* mask  = (const float*)d_in[3];
    const float* Cl    = (const float*)d_in[4];
    const float* W1    = (const float*)d_in[5];
    const float* b1    = (const float*)d_in[6];
    const float* W2    = (const float*)d_in[7];
    const float* b2    = (const float*)d_in[8];
    const float* tadj  = (const float*)d_in[9];
    const float* tfeat = (const float*)d_in[10];
    const float* Wlin  = (const float*)d_in[11];
    const float* blin  = (const float*)d_in[12];
    float* out = (float*)d_out;

    const int* src = ei;
    const int* dst = ei + EE;

    void *pA, *pB, *pC;
    cudaGetSymbolAddress(&pA, g_bufA);
    cudaGetSymbolAddress(&pB, g_bufB);
    cudaGetSymbolAddress(&pC, g_bufC);
    float* bufA = (float*)pA;
    float* bufB = (float*)pB;
    float* bufC = (float*)pC;

    cudaFuncSetAttribute(k_gemm, cudaFuncAttributeMaxDynamicSharedMemorySize, GEMM_SMEM);

    // g_cnt is zero at module load and re-zeroed by k_pr at the end of every launch
    k_fill<<<(EE + 255) / 256, 256>>>(src, dst);

    k_gemm<<<(NN + 63) / 64, 128, GEMM_SMEM>>>(x, W1, bufA, NN, FIN, FIN);
    k_gather<true><<<NN / 16, 256>>>((const float4*)bufA, (const float4*)b1, (float4*)bufB);

    k_gemm<<<(NN + 63) / 64, 128, GEMM_SMEM>>>(bufB, W2, bufA, NN, HID, HID);
    k_gather<false><<<NN / 16, 256>>>((const float4*)bufA, (const float4*)b2, (float4*)bufC);

    k_pr<<<(NN + 63) / 64, 256>>>(bufC, tfeat, tadj);

    k_dist<<<NN / NBD, 160>>>(bufC, nbr, mask, Cl, tadj, Wlin, blin, out);
}